// round 12
// baseline (speedup 1.0000x reference)
#include <cuda_runtime.h>
#include <cuda_fp16.h>
#include <cstdint>

#define DI __device__ __forceinline__

static constexpr int NN  = 8192;
static constexpr int DIM = 256;

// ---------------- scratch (device globals; allocation forbidden) -----------
__device__ __align__(1024) __half g_adjh[(size_t)NN * NN];  // fp16 adj (128 MB)
__device__ __align__(1024) float  g_dis[NN];                // rsqrt(1 + rowsum(adj))
__device__ __align__(1024) __half g_Mth[(size_t)DIM * NN];  // M^T [n][j] fp16 (B layout)
__device__ __align__(1024) __half g_Mrow[(size_t)NN * DIM]; // M   [j][n] fp16 (epilogue)
__device__ __align__(1024) __half g_xh[NN * DIM];           // x fp16
__device__ __align__(1024) __half g_Wh[DIM * DIM];          // W^T fp16

// ---------------- helpers ----------------
DI uint32_t h2_u32(__half2 h) { return *reinterpret_cast<uint32_t*>(&h); }
DI uint32_t packh2(float f0, float f1) {
    __half2 h = __floats2half2_rn(f0, f1);
    return h2_u32(h);
}
DI uint32_t smem_u32(const void* p) {
    uint32_t a;
    asm("{ .reg .u64 t; cvta.to.shared.u64 t, %1; cvt.u32.u64 %0, t; }" : "=r"(a) : "l"(p));
    return a;
}
DI void cp16(uint32_t s, const void* g) {
    asm volatile("cp.async.cg.shared.global [%0], [%1], 16;" :: "r"(s), "l"(g) : "memory");
}
DI void cp_commit() { asm volatile("cp.async.commit_group;" ::: "memory"); }
template <int N> DI void cp_wait() {
    asm volatile("cp.async.wait_group %0;" :: "n"(N) : "memory");
}
DI uint32_t lds32(uint32_t a) {
    uint32_t v;
    asm volatile("ld.shared.b32 %0, [%1];" : "=r"(v) : "r"(a));
    return v;
}
DI void mma_f16(float* d, const uint32_t* a, const uint32_t* b) {
    asm volatile(
        "mma.sync.aligned.m16n8k16.row.col.f32.f16.f16.f32 "
        "{%0,%1,%2,%3}, {%4,%5,%6,%7}, {%8,%9}, {%0,%1,%2,%3};"
        : "+f"(d[0]), "+f"(d[1]), "+f"(d[2]), "+f"(d[3])
        : "r"(a[0]), "r"(a[1]), "r"(a[2]), "r"(a[3]), "r"(b[0]), "r"(b[1]));
}
DI uint32_t sw128(uint32_t off) { return off ^ ((off >> 3) & 0x70); }

// ---------------- SMEM layout ----------------
// Tiles: 128 rows x 64 fp16 (128 B rows, SW128). K per stage = 64.
static constexpr int NST     = 4;
static constexpr int T_BYTES = 128 * 128;          // 16 KB
static constexpr int STAGE   = 2 * T_BYTES;        // 32 KB
static constexpr int DSMEM   = NST * STAGE;        // 128 KB

// ------ degree + convert: g_dis[i] = rsqrt(1+rowsum), g_adjh = fp16(adj) ---
__global__ void __launch_bounds__(256) degree_kernel(const float* __restrict__ adj) {
    const int i = blockIdx.x;
    const float4* row = reinterpret_cast<const float4*>(adj + (size_t)i * NN);
    uint4* orow = reinterpret_cast<uint4*>(g_adjh + (size_t)i * NN);
    float s = 0.f;
    for (int t = threadIdx.x; t < NN / 8; t += 256) {
        float4 v0 = row[2 * t], v1 = row[2 * t + 1];
        s += ((v0.x + v0.y) + (v0.z + v0.w)) + ((v1.x + v1.y) + (v1.z + v1.w));
        uint4 o;
        o.x = packh2(v0.x, v0.y);
        o.y = packh2(v0.z, v0.w);
        o.z = packh2(v1.x, v1.y);
        o.w = packh2(v1.z, v1.w);
        orow[t] = o;
    }
    for (int off = 16; off > 0; off >>= 1) s += __shfl_xor_sync(0xFFFFFFFFu, s, off);
    __shared__ float ws[8];
    if ((threadIdx.x & 31) == 0) ws[threadIdx.x >> 5] = s;
    __syncthreads();
    if (threadIdx.x == 0) {
        float t = 0.f;
        #pragma unroll
        for (int k = 0; k < 8; k++) t += ws[k];
        g_dis[i] = rsqrtf(t + 1.0f);
    }
}

// ---------------- prep: x -> fp16, W^T -> fp16 -----------------------------
__global__ void __launch_bounds__(256) prep_x_kernel(const float4* __restrict__ x) {
    int total = NN * DIM / 8;
    for (int t = blockIdx.x * blockDim.x + threadIdx.x; t < total; t += gridDim.x * blockDim.x) {
        float4 v0 = x[2 * t], v1 = x[2 * t + 1];
        uint4 o;
        o.x = packh2(v0.x, v0.y);
        o.y = packh2(v0.z, v0.w);
        o.z = packh2(v1.x, v1.y);
        o.w = packh2(v1.z, v1.w);
        reinterpret_cast<uint4*>(g_xh)[t] = o;
    }
}
__global__ void __launch_bounds__(256) prep_w_kernel(const float* __restrict__ W) {
    int n = blockIdx.x, k = threadIdx.x;
    g_Wh[n * DIM + k] = __float2half_rn(W[k * DIM + n]);
}

// -------- fp16 mma.sync GEMM: C[128x128] = A[128xK] @ B[128xK]^T -----------
// 512 threads, warp grid 4(M) x 4(N), warp tile 32x32.
// EPI=0: A=g_xh (lda=256, KT=4),     B=g_Wh.  C -> g_Mth (smem transpose) + g_Mrow
// EPI=1: A=g_adjh (lda=8192,KT=128), B=g_Mth. C -> out=relu(dis_i*(acc+M[i][n])+b[n])
template <int EPI>
__global__ void __launch_bounds__(512, 1)
gemm_k(const __half* __restrict__ A, int lda, int KT,
       const float* __restrict__ bias, float* __restrict__ out) {
    const __half* __restrict__ B = EPI ? (const __half*)g_Mth : (const __half*)g_Wh;
    const int ldb = EPI ? NN : DIM;

    extern __shared__ char smem[];
    const uint32_t sb = smem_u32(smem);
    const int tid = threadIdx.x, lane = tid & 31, wid = tid >> 5;
    const int wm = wid & 3, wn = wid >> 2;          // warp grid 4(M) x 4(N)
    const size_t mrow0 = (size_t)blockIdx.x * 128;
    const size_t nrow0 = (size_t)blockIdx.y * 128;

    float acc[2][4][4];
    #pragma unroll
    for (int mi = 0; mi < 2; mi++)
        #pragma unroll
        for (int ni = 0; ni < 4; ni++)
            #pragma unroll
            for (int r = 0; r < 4; r++) acc[mi][ni][r] = 0.f;

    // copy geometry: per tile 1024 x 16B chunks; 512 threads -> 2 chunks each
    const int crow = tid >> 3, cseg = tid & 7;       // chunk c = tid (+512 -> +64 rows)
    const uint32_t sdst = sw128((uint32_t)(crow * 128 + cseg * 16));
    const __half* gA = A + (mrow0 + crow) * (size_t)lda + cseg * 8;
    const __half* gB = B + (nrow0 + crow) * (size_t)ldb + cseg * 8;
    const size_t stepA = 64ull * (size_t)lda;        // +64 rows (q stride)
    const size_t stepB = 64ull * (size_t)ldb;

    auto load_stage = [&](int kt) {
        const int s = kt & (NST - 1);
        const uint32_t stA = sb + s * STAGE;
        const uint32_t stB = stA + T_BYTES;
        const int k0 = kt * 64;
        #pragma unroll
        for (int q = 0; q < 2; q++)
            cp16(stA + sdst + q * (64 * 128), gA + k0 + q * stepA);
        #pragma unroll
        for (int q = 0; q < 2; q++)
            cp16(stB + sdst + q * (64 * 128), gB + k0 + q * stepB);
        cp_commit();
    };

    for (int p = 0; p < NST - 1 && p < KT; p++) load_stage(p);

    // fragment geometry (m16n8k16, fp16, 128B SW128 rows)
    const int arow_base = wm * 32 + (lane >> 2);     // + mi*16, +8
    const int brow_base = wn * 32 + (lane >> 2);     // + ni*8
    const int kbl = (lane & 3) * 4;                  // byte col base

    for (int kt = 0; kt < KT; kt++) {
        cp_wait<NST - 2>();
        __syncthreads();
        const int s = kt & (NST - 1);
        const uint32_t stA = sb + s * STAGE;
        const uint32_t stB = stA + T_BYTES;

        #pragma unroll
        for (int ks = 0; ks < 4; ks++) {
            const int kb = ks * 32 + kbl;
            uint32_t bf[4][2];
            #pragma unroll
            for (int ni = 0; ni < 4; ni++) {
                int br = brow_base + ni * 8;
                bf[ni][0] = lds32(stB + sw128((uint32_t)(br * 128 + kb)));
                bf[ni][1] = lds32(stB + sw128((uint32_t)(br * 128 + kb + 16)));
            }
            #pragma unroll
            for (int mi = 0; mi < 2; mi++) {
                int ar = arow_base + mi * 16;
                uint32_t af[4];
                af[0] = lds32(stA + sw128((uint32_t)(ar * 128 + kb)));
                af[1] = lds32(stA + sw128((uint32_t)((ar + 8) * 128 + kb)));
                af[2] = lds32(stA + sw128((uint32_t)(ar * 128 + kb + 16)));
                af[3] = lds32(stA + sw128((uint32_t)((ar + 8) * 128 + kb + 16)));
                #pragma unroll
                for (int ni = 0; ni < 4; ni++) mma_f16(acc[mi][ni], af, bf[ni]);
            }
        }
        __syncthreads();
        if (kt + NST - 1 < KT) load_stage(kt + NST - 1);
    }

    // ---------------- epilogue ----------------
    if (EPI == 0) {
        // scale by dis_j; write g_Mrow (4B) and g_Mth via SMEM transpose (16B rows).
        __syncthreads();                      // pipeline smem dead — reuse
        __half* sC = reinterpret_cast<__half*>(smem);
        constexpr int PITCH = 136;            // halves; 272 B rows (16B-aligned)
        #pragma unroll
        for (int mi = 0; mi < 2; mi++) {
            const int r0 = wm * 32 + mi * 16 + (lane >> 2);
            const size_t j0 = mrow0 + r0;
            const float dis0 = g_dis[j0], dis1 = g_dis[j0 + 8];
            #pragma unroll
            for (int ni = 0; ni < 4; ni++) {
                const int n = wn * 32 + ni * 8 + (lane & 3) * 2;   // local n
                uint32_t p0 = packh2(dis0 * acc[mi][ni][0], dis0 * acc[mi][ni][1]);
                uint32_t p1 = packh2(dis1 * acc[mi][ni][2], dis1 * acc[mi][ni][3]);
                *reinterpret_cast<uint32_t*>(g_Mrow + j0 * DIM + nrow0 + n)       = p0;
                *reinterpret_cast<uint32_t*>(g_Mrow + (j0 + 8) * DIM + nrow0 + n) = p1;
                __half2 h0 = *reinterpret_cast<__half2*>(&p0);
                __half2 h1 = *reinterpret_cast<__half2*>(&p1);
                sC[n * PITCH + r0]           = __low2half(h0);
                sC[(n + 1) * PITCH + r0]     = __high2half(h0);
                sC[n * PITCH + r0 + 8]       = __low2half(h1);
                sC[(n + 1) * PITCH + r0 + 8] = __high2half(h1);
            }
        }
        __syncthreads();
        // 512 threads: n = tid>>2 (128 rows), seg = tid&3 -> 32 halves each
        const int n = tid >> 2, seg = tid & 3;
        const __half* src = sC + n * PITCH + seg * 32;
        __half* dst = g_Mth + (nrow0 + n) * (size_t)NN + mrow0 + seg * 32;
        #pragma unroll
        for (int w = 0; w < 4; w++)
            reinterpret_cast<uint4*>(dst)[w] = reinterpret_cast<const uint4*>(src)[w];
    } else {
        #pragma unroll
        for (int mi = 0; mi < 2; mi++) {
            const int r0 = wm * 32 + mi * 16 + (lane >> 2);
            const size_t i0 = mrow0 + r0;
            const float dis0 = g_dis[i0], dis1 = g_dis[i0 + 8];
            #pragma unroll
            for (int ni = 0; ni < 4; ni++) {
                const int n = (int)nrow0 + wn * 32 + ni * 8 + (lane & 3) * 2;
                const float b0 = bias[n], b1 = bias[n + 1];
                __half2 mh0 = *reinterpret_cast<const __half2*>(g_Mrow + i0 * DIM + n);
                __half2 mh1 = *reinterpret_cast<const __half2*>(g_Mrow + (i0 + 8) * DIM + n);
                float2 mf0 = __half22float2(mh0);
                float2 mf1 = __half22float2(mh1);
                float v0 = dis0 * (acc[mi][ni][0] + mf0.x) + b0;
                float v1 = dis0 * (acc[mi][ni][1] + mf0.y) + b1;
                float v2 = dis1 * (acc[mi][ni][2] + mf1.x) + b0;
                float v3 = dis1 * (acc[mi][ni][3] + mf1.y) + b1;
                float2 p0 = make_float2(v0 > 0.f ? v0 : 0.f, v1 > 0.f ? v1 : 0.f);
                float2 p1 = make_float2(v2 > 0.f ? v2 : 0.f, v3 > 0.f ? v3 : 0.f);
                *reinterpret_cast<float2*>(out + i0 * DIM + n)       = p0;
                *reinterpret_cast<float2*>(out + (i0 + 8) * DIM + n) = p1;
            }
        }
    }
}

// ---------------- launch ----------------
extern "C" void kernel_launch(void* const* d_in, const int* in_sizes, int n_in,
                              void* d_out, int out_size) {
    const float* x   = (const float*)d_in[0];
    const float* adj = (const float*)d_in[1];
    const float* W   = (const float*)d_in[2];
    const float* b   = (const float*)d_in[3];
    float* out = (float*)d_out;

    cudaFuncSetAttribute(gemm_k<0>, cudaFuncAttributeMaxDynamicSharedMemorySize, DSMEM);
    cudaFuncSetAttribute(gemm_k<1>, cudaFuncAttributeMaxDynamicSharedMemorySize, DSMEM);

    prep_w_kernel<<<DIM, DIM>>>(W);
    prep_x_kernel<<<512, 256>>>((const float4*)x);
    degree_kernel<<<NN, 256>>>(adj);

    __half* xh;   cudaGetSymbolAddress((void**)&xh,  g_xh);
    __half* adjh; cudaGetSymbolAddress((void**)&adjh, g_adjh);

    gemm_k<0><<<dim3(NN / 128, 2), 512, DSMEM>>>(xh, DIM, DIM / 64, nullptr, nullptr);
    gemm_k<1><<<dim3(NN / 128, 2), 512, DSMEM>>>(adjh, NN, NN / 64, b, out);
}

// round 13
// speedup vs baseline: 1.0170x; 1.0170x over previous
#include <cuda_runtime.h>
#include <cuda_fp16.h>
#include <cstdint>

#define DI __device__ __forceinline__

static constexpr int NN  = 8192;
static constexpr int DIM = 256;

// ---------------- scratch (device globals; allocation forbidden) -----------
__device__ __align__(1024) __half g_adjh[(size_t)NN * NN];  // fp16 adj (128 MB)
__device__ __align__(1024) float  g_dis[NN];                // rsqrt(1 + rowsum(adj))
__device__ __align__(1024) __half g_Mth[(size_t)DIM * NN];  // M^T [n][j] fp16; M' then dis_j*M'
__device__ __align__(1024) __half g_Mrow[(size_t)NN * DIM]; // M'  [j][n] fp16 (unscaled)
__device__ __align__(1024) __half g_xh[NN * DIM];           // x fp16
__device__ __align__(1024) __half g_Wh[DIM * DIM];          // W^T fp16

// ---------------- helpers ----------------
DI uint32_t h2_u32(__half2 h) { return *reinterpret_cast<uint32_t*>(&h); }
DI uint32_t packh2(float f0, float f1) {
    __half2 h = __floats2half2_rn(f0, f1);
    return h2_u32(h);
}
DI uint32_t smem_u32(const void* p) {
    uint32_t a;
    asm("{ .reg .u64 t; cvta.to.shared.u64 t, %1; cvt.u32.u64 %0, t; }" : "=r"(a) : "l"(p));
    return a;
}
DI void cp16(uint32_t s, const void* g) {
    asm volatile("cp.async.cg.shared.global [%0], [%1], 16;" :: "r"(s), "l"(g) : "memory");
}
DI void cp_commit() { asm volatile("cp.async.commit_group;" ::: "memory"); }
template <int N> DI void cp_wait() {
    asm volatile("cp.async.wait_group %0;" :: "n"(N) : "memory");
}
DI uint32_t lds32(uint32_t a) {
    uint32_t v;
    asm volatile("ld.shared.b32 %0, [%1];" : "=r"(v) : "r"(a));
    return v;
}
DI void mma_f16(float* d, const uint32_t* a, const uint32_t* b) {
    asm volatile(
        "mma.sync.aligned.m16n8k16.row.col.f32.f16.f16.f32 "
        "{%0,%1,%2,%3}, {%4,%5,%6,%7}, {%8,%9}, {%0,%1,%2,%3};"
        : "+f"(d[0]), "+f"(d[1]), "+f"(d[2]), "+f"(d[3])
        : "r"(a[0]), "r"(a[1]), "r"(a[2]), "r"(a[3]), "r"(b[0]), "r"(b[1]));
}
DI uint32_t sw128(uint32_t off) { return off ^ ((off >> 3) & 0x70); }

// ---------------- SMEM layout ----------------
static constexpr int NST     = 4;
static constexpr int T_BYTES = 128 * 128;          // 16 KB
static constexpr int STAGE   = 2 * T_BYTES;        // 32 KB
static constexpr int DSMEM   = NST * STAGE;        // 128 KB

// ------ degree + convert: g_dis[i] = rsqrt(1+rowsum), g_adjh = fp16(adj) ---
__global__ void __launch_bounds__(256) degree_kernel(const float* __restrict__ adj) {
    const int i = blockIdx.x;
    const float4* row = reinterpret_cast<const float4*>(adj + (size_t)i * NN);
    uint4* orow = reinterpret_cast<uint4*>(g_adjh + (size_t)i * NN);
    float s = 0.f;
    for (int t = threadIdx.x; t < NN / 8; t += 256) {
        float4 v0 = row[2 * t], v1 = row[2 * t + 1];
        s += ((v0.x + v0.y) + (v0.z + v0.w)) + ((v1.x + v1.y) + (v1.z + v1.w));
        uint4 o;
        o.x = packh2(v0.x, v0.y);
        o.y = packh2(v0.z, v0.w);
        o.z = packh2(v1.x, v1.y);
        o.w = packh2(v1.z, v1.w);
        orow[t] = o;
    }
    for (int off = 16; off > 0; off >>= 1) s += __shfl_xor_sync(0xFFFFFFFFu, s, off);
    __shared__ float ws[8];
    if ((threadIdx.x & 31) == 0) ws[threadIdx.x >> 5] = s;
    __syncthreads();
    if (threadIdx.x == 0) {
        float t = 0.f;
        #pragma unroll
        for (int k = 0; k < 8; k++) t += ws[k];
        g_dis[i] = rsqrtf(t + 1.0f);
    }
}

// ---------------- prep: x -> fp16, W^T -> fp16 -----------------------------
__global__ void __launch_bounds__(256) prep_x_kernel(const float4* __restrict__ x) {
    int total = NN * DIM / 8;
    for (int t = blockIdx.x * blockDim.x + threadIdx.x; t < total; t += gridDim.x * blockDim.x) {
        float4 v0 = x[2 * t], v1 = x[2 * t + 1];
        uint4 o;
        o.x = packh2(v0.x, v0.y);
        o.y = packh2(v0.z, v0.w);
        o.z = packh2(v1.x, v1.y);
        o.w = packh2(v1.z, v1.w);
        reinterpret_cast<uint4*>(g_xh)[t] = o;
    }
}
__global__ void __launch_bounds__(256) prep_w_kernel(const float* __restrict__ W) {
    int n = blockIdx.x, k = threadIdx.x;
    g_Wh[n * DIM + k] = __float2half_rn(W[k * DIM + n]);
}

// ---- scale M' in place: g_Mth[n][j] *= dis[j] (fp32 math) -----------------
__global__ void __launch_bounds__(256) scale_m_kernel() {
    const int t = blockIdx.x * 256 + threadIdx.x;    // 262144 uint4 total
    const int j = (t * 8) & (NN - 1);
    uint4 v = reinterpret_cast<uint4*>(g_Mth)[t];
    __half2* h = reinterpret_cast<__half2*>(&v);
    const float4 d0 = *reinterpret_cast<const float4*>(g_dis + j);
    const float4 d1 = *reinterpret_cast<const float4*>(g_dis + j + 4);
    float2 f;
    f = __half22float2(h[0]); h[0] = __floats2half2_rn(f.x * d0.x, f.y * d0.y);
    f = __half22float2(h[1]); h[1] = __floats2half2_rn(f.x * d0.z, f.y * d0.w);
    f = __half22float2(h[2]); h[2] = __floats2half2_rn(f.x * d1.x, f.y * d1.y);
    f = __half22float2(h[3]); h[3] = __floats2half2_rn(f.x * d1.z, f.y * d1.w);
    reinterpret_cast<uint4*>(g_Mth)[t] = v;
}

// -------- fp16 mma.sync GEMM: C[128x128] = A[128xK] @ B[128xK]^T -----------
// 512 threads, warp grid 4(M) x 4(N), warp tile 32x32.
// EPI=0: A=g_xh (KT=4),  B=g_Wh.  C = M' (NO dis) -> g_Mth (transpose) + g_Mrow
// EPI=1: A=g_adjh (KT=128), B=g_Mth(scaled). out=relu(dis_i*acc + dis_i^2*M'row + b)
template <int EPI>
__global__ void __launch_bounds__(512, 1)
gemm_k(const __half* __restrict__ A, int lda, int KT,
       const float* __restrict__ bias, float* __restrict__ out) {
    const __half* __restrict__ B = EPI ? (const __half*)g_Mth : (const __half*)g_Wh;
    const int ldb = EPI ? NN : DIM;

    extern __shared__ char smem[];
    const uint32_t sb = smem_u32(smem);
    const int tid = threadIdx.x, lane = tid & 31, wid = tid >> 5;
    const int wm = wid & 3, wn = wid >> 2;          // warp grid 4(M) x 4(N)
    const size_t mrow0 = (size_t)blockIdx.x * 128;
    const size_t nrow0 = (size_t)blockIdx.y * 128;

    float acc[2][4][4];
    #pragma unroll
    for (int mi = 0; mi < 2; mi++)
        #pragma unroll
        for (int ni = 0; ni < 4; ni++)
            #pragma unroll
            for (int r = 0; r < 4; r++) acc[mi][ni][r] = 0.f;

    // copy geometry: per tile 1024 x 16B chunks; 512 threads -> 2 chunks each
    const int crow = tid >> 3, cseg = tid & 7;
    const uint32_t sdst = sw128((uint32_t)(crow * 128 + cseg * 16));
    const __half* gA = A + (mrow0 + crow) * (size_t)lda + cseg * 8;
    const __half* gB = B + (nrow0 + crow) * (size_t)ldb + cseg * 8;
    const size_t stepA = 64ull * (size_t)lda;
    const size_t stepB = 64ull * (size_t)ldb;

    auto load_stage = [&](int kt) {
        const int s = kt & (NST - 1);
        const uint32_t stA = sb + s * STAGE;
        const uint32_t stB = stA + T_BYTES;
        const int k0 = kt * 64;
        #pragma unroll
        for (int q = 0; q < 2; q++)
            cp16(stA + sdst + q * (64 * 128), gA + k0 + q * stepA);
        #pragma unroll
        for (int q = 0; q < 2; q++)
            cp16(stB + sdst + q * (64 * 128), gB + k0 + q * stepB);
        cp_commit();
    };

    for (int p = 0; p < NST - 1 && p < KT; p++) load_stage(p);

    const int arow_base = wm * 32 + (lane >> 2);     // + mi*16, +8
    const int brow_base = wn * 32 + (lane >> 2);     // + ni*8
    const int kbl = (lane & 3) * 4;                  // byte col base

    for (int kt = 0; kt < KT; kt++) {
        cp_wait<NST - 2>();
        __syncthreads();
        const int s = kt & (NST - 1);
        const uint32_t stA = sb + s * STAGE;
        const uint32_t stB = stA + T_BYTES;

        #pragma unroll
        for (int ks = 0; ks < 4; ks++) {
            const int kb = ks * 32 + kbl;
            uint32_t bf[4][2];
            #pragma unroll
            for (int ni = 0; ni < 4; ni++) {
                int br = brow_base + ni * 8;
                bf[ni][0] = lds32(stB + sw128((uint32_t)(br * 128 + kb)));
                bf[ni][1] = lds32(stB + sw128((uint32_t)(br * 128 + kb + 16)));
            }
            #pragma unroll
            for (int mi = 0; mi < 2; mi++) {
                int ar = arow_base + mi * 16;
                uint32_t af[4];
                af[0] = lds32(stA + sw128((uint32_t)(ar * 128 + kb)));
                af[1] = lds32(stA + sw128((uint32_t)((ar + 8) * 128 + kb)));
                af[2] = lds32(stA + sw128((uint32_t)(ar * 128 + kb + 16)));
                af[3] = lds32(stA + sw128((uint32_t)((ar + 8) * 128 + kb + 16)));
                #pragma unroll
                for (int ni = 0; ni < 4; ni++) mma_f16(acc[mi][ni], af, bf[ni]);
            }
        }
        __syncthreads();
        if (kt + NST - 1 < KT) load_stage(kt + NST - 1);
    }

    // ---------------- epilogue ----------------
    if (EPI == 0) {
        // write M' (unscaled): g_Mrow direct + g_Mth via SMEM transpose.
        __syncthreads();                      // pipeline smem dead — reuse
        __half* sC = reinterpret_cast<__half*>(smem);
        constexpr int PITCH = 136;            // halves; 272 B rows (16B-aligned)
        #pragma unroll
        for (int mi = 0; mi < 2; mi++) {
            const int r0 = wm * 32 + mi * 16 + (lane >> 2);
            const size_t j0 = mrow0 + r0;
            #pragma unroll
            for (int ni = 0; ni < 4; ni++) {
                const int n = wn * 32 + ni * 8 + (lane & 3) * 2;   // local n
                uint32_t p0 = packh2(acc[mi][ni][0], acc[mi][ni][1]);
                uint32_t p1 = packh2(acc[mi][ni][2], acc[mi][ni][3]);
                *reinterpret_cast<uint32_t*>(g_Mrow + j0 * DIM + nrow0 + n)       = p0;
                *reinterpret_cast<uint32_t*>(g_Mrow + (j0 + 8) * DIM + nrow0 + n) = p1;
                __half2 h0 = *reinterpret_cast<__half2*>(&p0);
                __half2 h1 = *reinterpret_cast<__half2*>(&p1);
                sC[n * PITCH + r0]           = __low2half(h0);
                sC[(n + 1) * PITCH + r0]     = __high2half(h0);
                sC[n * PITCH + r0 + 8]       = __low2half(h1);
                sC[(n + 1) * PITCH + r0 + 8] = __high2half(h1);
            }
        }
        __syncthreads();
        const int n = tid >> 2, seg = tid & 3;       // 128 rows x 4 segs x 32 halves
        const __half* src = sC + n * PITCH + seg * 32;
        __half* dst = g_Mth + (nrow0 + n) * (size_t)NN + mrow0 + seg * 32;
        #pragma unroll
        for (int w = 0; w < 4; w++)
            reinterpret_cast<uint4*>(dst)[w] = reinterpret_cast<const uint4*>(src)[w];
    } else {
        #pragma unroll
        for (int mi = 0; mi < 2; mi++) {
            const int r0 = wm * 32 + mi * 16 + (lane >> 2);
            const size_t i0 = mrow0 + r0;
            const float dis0 = g_dis[i0], dis1 = g_dis[i0 + 8];
            const float ds0 = dis0 * dis0, ds1 = dis1 * dis1;
            #pragma unroll
            for (int ni = 0; ni < 4; ni++) {
                const int n = (int)nrow0 + wn * 32 + ni * 8 + (lane & 3) * 2;
                const float b0 = bias[n], b1 = bias[n + 1];
                __half2 mh0 = *reinterpret_cast<const __half2*>(g_Mrow + i0 * DIM + n);
                __half2 mh1 = *reinterpret_cast<const __half2*>(g_Mrow + (i0 + 8) * DIM + n);
                float2 mf0 = __half22float2(mh0);
                float2 mf1 = __half22float2(mh1);
                float v0 = dis0 * acc[mi][ni][0] + ds0 * mf0.x + b0;
                float v1 = dis0 * acc[mi][ni][1] + ds0 * mf0.y + b1;
                float v2 = dis1 * acc[mi][ni][2] + ds1 * mf1.x + b0;
                float v3 = dis1 * acc[mi][ni][3] + ds1 * mf1.y + b1;
                float2 p0 = make_float2(v0 > 0.f ? v0 : 0.f, v1 > 0.f ? v1 : 0.f);
                float2 p1 = make_float2(v2 > 0.f ? v2 : 0.f, v3 > 0.f ? v3 : 0.f);
                *reinterpret_cast<float2*>(out + i0 * DIM + n)       = p0;
                *reinterpret_cast<float2*>(out + (i0 + 8) * DIM + n) = p1;
            }
        }
    }
}

// ---------------- launch ----------------
extern "C" void kernel_launch(void* const* d_in, const int* in_sizes, int n_in,
                              void* d_out, int out_size) {
    const float* x   = (const float*)d_in[0];
    const float* adj = (const float*)d_in[1];
    const float* W   = (const float*)d_in[2];
    const float* b   = (const float*)d_in[3];
    float* out = (float*)d_out;

    static cudaStream_t s1 = nullptr;
    static cudaEvent_t ef = nullptr, ej = nullptr;
    if (s1 == nullptr) {                 // lazy init on the (non-captured) first call
        cudaStreamCreateWithFlags(&s1, cudaStreamNonBlocking);
        cudaEventCreateWithFlags(&ef, cudaEventDisableTiming);
        cudaEventCreateWithFlags(&ej, cudaEventDisableTiming);
        cudaFuncSetAttribute(gemm_k<0>, cudaFuncAttributeMaxDynamicSharedMemorySize, DSMEM);
        cudaFuncSetAttribute(gemm_k<1>, cudaFuncAttributeMaxDynamicSharedMemorySize, DSMEM);
    }

    __half* xh;   cudaGetSymbolAddress((void**)&xh,  g_xh);
    __half* adjh; cudaGetSymbolAddress((void**)&adjh, g_adjh);

    // fork: side stream computes M' = xW while main stream does degree+convert
    cudaEventRecord(ef, 0);
    cudaStreamWaitEvent(s1, ef, 0);
    prep_w_kernel<<<DIM, DIM, 0, s1>>>(W);
    prep_x_kernel<<<512, 256, 0, s1>>>((const float4*)x);
    gemm_k<0><<<dim3(NN / 128, 2), 512, DSMEM, s1>>>(xh, DIM, DIM / 64, nullptr, nullptr);
    cudaEventRecord(ej, s1);

    degree_kernel<<<NN, 256>>>(adj);

    // join, then scale M' by dis_j and run the big GEMM
    cudaStreamWaitEvent(0, ej, 0);
    scale_m_kernel<<<DIM * NN / 8 / 256, 256>>>();
    gemm_k<1><<<dim3(NN / 128, 2), 512, DSMEM>>>(adjh, NN, NN / 64, b, out);
}

// round 14
// speedup vs baseline: 1.0211x; 1.0040x over previous
#include <cuda_runtime.h>
#include <cuda_fp16.h>
#include <cstdint>

#define DI __device__ __forceinline__

static constexpr int NN  = 8192;
static constexpr int DIM = 256;

// ---------------- scratch (device globals; allocation forbidden) -----------
__device__ __align__(1024) __half g_adjh[(size_t)NN * NN];  // fp16 adj (128 MB)
__device__ __align__(1024) float  g_dis[NN];                // rsqrt(1 + rowsum(adj))
__device__ __align__(1024) __half g_Mth[(size_t)DIM * NN];  // M^T [n][j] fp16; M' then dis_j*M'
__device__ __align__(1024) __half g_Mrow[(size_t)NN * DIM]; // M'  [j][n] fp16 (unscaled)
__device__ __align__(1024) __half g_xh[NN * DIM];           // x fp16
__device__ __align__(1024) __half g_Wh[DIM * DIM];          // W^T fp16

// ---------------- helpers ----------------
DI uint32_t h2_u32(__half2 h) { return *reinterpret_cast<uint32_t*>(&h); }
DI uint32_t packh2(float f0, float f1) {
    __half2 h = __floats2half2_rn(f0, f1);
    return h2_u32(h);
}
DI uint32_t smem_u32(const void* p) {
    uint32_t a;
    asm("{ .reg .u64 t; cvta.to.shared.u64 t, %1; cvt.u32.u64 %0, t; }" : "=r"(a) : "l"(p));
    return a;
}
DI void cp16(uint32_t s, const void* g) {
    asm volatile("cp.async.cg.shared.global [%0], [%1], 16;" :: "r"(s), "l"(g) : "memory");
}
DI void cp_commit() { asm volatile("cp.async.commit_group;" ::: "memory"); }
template <int N> DI void cp_wait() {
    asm volatile("cp.async.wait_group %0;" :: "n"(N) : "memory");
}
DI uint32_t lds32(uint32_t a) {
    uint32_t v;
    asm volatile("ld.shared.b32 %0, [%1];" : "=r"(v) : "r"(a));
    return v;
}
DI void mma_f16(float* d, const uint32_t* a, const uint32_t* b) {
    asm volatile(
        "mma.sync.aligned.m16n8k16.row.col.f32.f16.f16.f32 "
        "{%0,%1,%2,%3}, {%4,%5,%6,%7}, {%8,%9}, {%0,%1,%2,%3};"
        : "+f"(d[0]), "+f"(d[1]), "+f"(d[2]), "+f"(d[3])
        : "r"(a[0]), "r"(a[1]), "r"(a[2]), "r"(a[3]), "r"(b[0]), "r"(b[1]));
}
DI uint32_t sw128(uint32_t off) { return off ^ ((off >> 3) & 0x70); }

// ---------------- SMEM layout ----------------
static constexpr int NST     = 4;
static constexpr int T_BYTES = 128 * 128;          // 16 KB
static constexpr int STAGE   = 2 * T_BYTES;        // 32 KB
static constexpr int DSMEM   = NST * STAGE;        // 128 KB

// ------ degree + convert (persistent, 1 wave): dis + adjh ------------------
__global__ void __launch_bounds__(256) degree_kernel(const float* __restrict__ adj) {
    __shared__ float ws[8];
    for (int i = blockIdx.x; i < NN; i += gridDim.x) {
        const float4* row = reinterpret_cast<const float4*>(adj + (size_t)i * NN);
        uint4* orow = reinterpret_cast<uint4*>(g_adjh + (size_t)i * NN);
        float s = 0.f;
        for (int t = threadIdx.x; t < NN / 8; t += 256) {
            float4 v0 = row[2 * t], v1 = row[2 * t + 1];
            s += ((v0.x + v0.y) + (v0.z + v0.w)) + ((v1.x + v1.y) + (v1.z + v1.w));
            uint4 o;
            o.x = packh2(v0.x, v0.y);
            o.y = packh2(v0.z, v0.w);
            o.z = packh2(v1.x, v1.y);
            o.w = packh2(v1.z, v1.w);
            orow[t] = o;
        }
        for (int off = 16; off > 0; off >>= 1) s += __shfl_xor_sync(0xFFFFFFFFu, s, off);
        if ((threadIdx.x & 31) == 0) ws[threadIdx.x >> 5] = s;
        __syncthreads();
        if (threadIdx.x == 0) {
            float t = 0.f;
            #pragma unroll
            for (int k = 0; k < 8; k++) t += ws[k];
            g_dis[i] = rsqrtf(t + 1.0f);
        }
        __syncthreads();   // ws reused next iteration
    }
}

// ---------------- prep (fused): x -> fp16, W^T -> fp16 ---------------------
__global__ void __launch_bounds__(256) prep_xw_kernel(const float4* __restrict__ x,
                                                      const float* __restrict__ W) {
    if (blockIdx.x < 512) {
        int total = NN * DIM / 8;
        for (int t = blockIdx.x * 256 + threadIdx.x; t < total; t += 512 * 256) {
            float4 v0 = x[2 * t], v1 = x[2 * t + 1];
            uint4 o;
            o.x = packh2(v0.x, v0.y);
            o.y = packh2(v0.z, v0.w);
            o.z = packh2(v1.x, v1.y);
            o.w = packh2(v1.z, v1.w);
            reinterpret_cast<uint4*>(g_xh)[t] = o;
        }
    } else {
        int n = blockIdx.x - 512, k = threadIdx.x;
        g_Wh[n * DIM + k] = __float2half_rn(W[k * DIM + n]);
    }
}

// ---- scale M' in place: g_Mth[n][j] *= dis[j] (fp32 math) -----------------
__global__ void __launch_bounds__(256) scale_m_kernel() {
    const int t = blockIdx.x * 256 + threadIdx.x;    // 262144 uint4 total
    const int j = (t * 8) & (NN - 1);
    uint4 v = reinterpret_cast<uint4*>(g_Mth)[t];
    __half2* h = reinterpret_cast<__half2*>(&v);
    const float4 d0 = *reinterpret_cast<const float4*>(g_dis + j);
    const float4 d1 = *reinterpret_cast<const float4*>(g_dis + j + 4);
    float2 f;
    f = __half22float2(h[0]); h[0] = __floats2half2_rn(f.x * d0.x, f.y * d0.y);
    f = __half22float2(h[1]); h[1] = __floats2half2_rn(f.x * d0.z, f.y * d0.w);
    f = __half22float2(h[2]); h[2] = __floats2half2_rn(f.x * d1.x, f.y * d1.y);
    f = __half22float2(h[3]); h[3] = __floats2half2_rn(f.x * d1.z, f.y * d1.w);
    reinterpret_cast<uint4*>(g_Mth)[t] = v;
}

// -------- fp16 mma.sync GEMM: C[128x128] = A[128xK] @ B[128xK]^T -----------
// 512 threads, warp grid 4(M) x 4(N), warp tile 32x32.
// EPI=0: A=g_xh (KT=4),  B=g_Wh.  C = M' (NO dis) -> g_Mth (transpose) + g_Mrow
// EPI=1: A=g_adjh (KT=128), B=g_Mth(scaled). out=relu(dis_i*acc + dis_i^2*M'row + b)
template <int EPI>
__global__ void __launch_bounds__(512, 1)
gemm_k(const __half* __restrict__ A, int lda, int KT,
       const float* __restrict__ bias, float* __restrict__ out) {
    const __half* __restrict__ B = EPI ? (const __half*)g_Mth : (const __half*)g_Wh;
    const int ldb = EPI ? NN : DIM;

    extern __shared__ char smem[];
    const uint32_t sb = smem_u32(smem);
    const int tid = threadIdx.x, lane = tid & 31, wid = tid >> 5;
    const int wm = wid & 3, wn = wid >> 2;          // warp grid 4(M) x 4(N)
    const size_t mrow0 = (size_t)blockIdx.x * 128;
    const size_t nrow0 = (size_t)blockIdx.y * 128;

    float acc[2][4][4];
    #pragma unroll
    for (int mi = 0; mi < 2; mi++)
        #pragma unroll
        for (int ni = 0; ni < 4; ni++)
            #pragma unroll
            for (int r = 0; r < 4; r++) acc[mi][ni][r] = 0.f;

    // copy geometry: per tile 1024 x 16B chunks; 512 threads -> 2 chunks each
    const int crow = tid >> 3, cseg = tid & 7;
    const uint32_t sdst = sw128((uint32_t)(crow * 128 + cseg * 16));
    const __half* gA = A + (mrow0 + crow) * (size_t)lda + cseg * 8;
    const __half* gB = B + (nrow0 + crow) * (size_t)ldb + cseg * 8;
    const size_t stepA = 64ull * (size_t)lda;
    const size_t stepB = 64ull * (size_t)ldb;

    auto load_stage = [&](int kt) {
        const int s = kt & (NST - 1);
        const uint32_t stA = sb + s * STAGE;
        const uint32_t stB = stA + T_BYTES;
        const int k0 = kt * 64;
        #pragma unroll
        for (int q = 0; q < 2; q++)
            cp16(stA + sdst + q * (64 * 128), gA + k0 + q * stepA);
        #pragma unroll
        for (int q = 0; q < 2; q++)
            cp16(stB + sdst + q * (64 * 128), gB + k0 + q * stepB);
        cp_commit();
    };

    for (int p = 0; p < NST - 1 && p < KT; p++) load_stage(p);

    const int arow_base = wm * 32 + (lane >> 2);     // + mi*16, +8
    const int brow_base = wn * 32 + (lane >> 2);     // + ni*8
    const int kbl = (lane & 3) * 4;                  // byte col base

    for (int kt = 0; kt < KT; kt++) {
        cp_wait<NST - 2>();
        __syncthreads();
        const int s = kt & (NST - 1);
        const uint32_t stA = sb + s * STAGE;
        const uint32_t stB = stA + T_BYTES;

        #pragma unroll
        for (int ks = 0; ks < 4; ks++) {
            const int kb = ks * 32 + kbl;
            uint32_t bf[4][2];
            #pragma unroll
            for (int ni = 0; ni < 4; ni++) {
                int br = brow_base + ni * 8;
                bf[ni][0] = lds32(stB + sw128((uint32_t)(br * 128 + kb)));
                bf[ni][1] = lds32(stB + sw128((uint32_t)(br * 128 + kb + 16)));
            }
            #pragma unroll
            for (int mi = 0; mi < 2; mi++) {
                int ar = arow_base + mi * 16;
                uint32_t af[4];
                af[0] = lds32(stA + sw128((uint32_t)(ar * 128 + kb)));
                af[1] = lds32(stA + sw128((uint32_t)((ar + 8) * 128 + kb)));
                af[2] = lds32(stA + sw128((uint32_t)(ar * 128 + kb + 16)));
                af[3] = lds32(stA + sw128((uint32_t)((ar + 8) * 128 + kb + 16)));
                #pragma unroll
                for (int ni = 0; ni < 4; ni++) mma_f16(acc[mi][ni], af, bf[ni]);
            }
        }
        __syncthreads();
        if (kt + NST - 1 < KT) load_stage(kt + NST - 1);
    }

    // ---------------- epilogue ----------------
    if (EPI == 0) {
        // write M' (unscaled): g_Mrow direct + g_Mth via SMEM transpose.
        __syncthreads();                      // pipeline smem dead — reuse
        __half* sC = reinterpret_cast<__half*>(smem);
        constexpr int PITCH = 136;            // halves; 272 B rows (16B-aligned)
        #pragma unroll
        for (int mi = 0; mi < 2; mi++) {
            const int r0 = wm * 32 + mi * 16 + (lane >> 2);
            const size_t j0 = mrow0 + r0;
            #pragma unroll
            for (int ni = 0; ni < 4; ni++) {
                const int n = wn * 32 + ni * 8 + (lane & 3) * 2;   // local n
                uint32_t p0 = packh2(acc[mi][ni][0], acc[mi][ni][1]);
                uint32_t p1 = packh2(acc[mi][ni][2], acc[mi][ni][3]);
                *reinterpret_cast<uint32_t*>(g_Mrow + j0 * DIM + nrow0 + n)       = p0;
                *reinterpret_cast<uint32_t*>(g_Mrow + (j0 + 8) * DIM + nrow0 + n) = p1;
                __half2 h0 = *reinterpret_cast<__half2*>(&p0);
                __half2 h1 = *reinterpret_cast<__half2*>(&p1);
                sC[n * PITCH + r0]           = __low2half(h0);
                sC[(n + 1) * PITCH + r0]     = __high2half(h0);
                sC[n * PITCH + r0 + 8]       = __low2half(h1);
                sC[(n + 1) * PITCH + r0 + 8] = __high2half(h1);
            }
        }
        __syncthreads();
        const int n = tid >> 2, seg = tid & 3;       // 128 rows x 4 segs x 32 halves
        const __half* src = sC + n * PITCH + seg * 32;
        __half* dst = g_Mth + (nrow0 + n) * (size_t)NN + mrow0 + seg * 32;
        #pragma unroll
        for (int w = 0; w < 4; w++)
            reinterpret_cast<uint4*>(dst)[w] = reinterpret_cast<const uint4*>(src)[w];
    } else {
        #pragma unroll
        for (int mi = 0; mi < 2; mi++) {
            const int r0 = wm * 32 + mi * 16 + (lane >> 2);
            const size_t i0 = mrow0 + r0;
            const float dis0 = g_dis[i0], dis1 = g_dis[i0 + 8];
            const float ds0 = dis0 * dis0, ds1 = dis1 * dis1;
            #pragma unroll
            for (int ni = 0; ni < 4; ni++) {
                const int n = (int)nrow0 + wn * 32 + ni * 8 + (lane & 3) * 2;
                const float b0 = bias[n], b1 = bias[n + 1];
                __half2 mh0 = *reinterpret_cast<const __half2*>(g_Mrow + i0 * DIM + n);
                __half2 mh1 = *reinterpret_cast<const __half2*>(g_Mrow + (i0 + 8) * DIM + n);
                float2 mf0 = __half22float2(mh0);
                float2 mf1 = __half22float2(mh1);
                float v0 = dis0 * acc[mi][ni][0] + ds0 * mf0.x + b0;
                float v1 = dis0 * acc[mi][ni][1] + ds0 * mf0.y + b1;
                float v2 = dis1 * acc[mi][ni][2] + ds1 * mf1.x + b0;
                float v3 = dis1 * acc[mi][ni][3] + ds1 * mf1.y + b1;
                float2 p0 = make_float2(v0 > 0.f ? v0 : 0.f, v1 > 0.f ? v1 : 0.f);
                float2 p1 = make_float2(v2 > 0.f ? v2 : 0.f, v3 > 0.f ? v3 : 0.f);
                *reinterpret_cast<float2*>(out + i0 * DIM + n)       = p0;
                *reinterpret_cast<float2*>(out + (i0 + 8) * DIM + n) = p1;
            }
        }
    }
}

// ---------------- launch ----------------
extern "C" void kernel_launch(void* const* d_in, const int* in_sizes, int n_in,
                              void* d_out, int out_size) {
    const float* x   = (const float*)d_in[0];
    const float* adj = (const float*)d_in[1];
    const float* W   = (const float*)d_in[2];
    const float* b   = (const float*)d_in[3];
    float* out = (float*)d_out;

    static cudaStream_t s1 = nullptr;
    static cudaEvent_t ef = nullptr, ej = nullptr;
    if (s1 == nullptr) {                 // lazy init on the (non-captured) first call
        cudaStreamCreateWithFlags(&s1, cudaStreamNonBlocking);
        cudaEventCreateWithFlags(&ef, cudaEventDisableTiming);
        cudaEventCreateWithFlags(&ej, cudaEventDisableTiming);
        cudaFuncSetAttribute(gemm_k<0>, cudaFuncAttributeMaxDynamicSharedMemorySize, DSMEM);
        cudaFuncSetAttribute(gemm_k<1>, cudaFuncAttributeMaxDynamicSharedMemorySize, DSMEM);
    }

    __half* xh;   cudaGetSymbolAddress((void**)&xh,  g_xh);
    __half* adjh; cudaGetSymbolAddress((void**)&adjh, g_adjh);

    // fork: side stream computes M' = xW while main stream does degree+convert
    cudaEventRecord(ef, 0);
    cudaStreamWaitEvent(s1, ef, 0);
    prep_xw_kernel<<<512 + DIM, 256, 0, s1>>>((const float4*)x, W);
    gemm_k<0><<<dim3(NN / 128, 2), 512, DSMEM, s1>>>(xh, DIM, DIM / 64, nullptr, nullptr);
    cudaEventRecord(ej, s1);

    degree_kernel<<<1184, 256>>>(adj);   // persistent: 1 wave (8 CTAs/SM x 148)

    // join, then scale M' by dis_j and run the big GEMM
    cudaStreamWaitEvent(0, ej, 0);
    scale_m_kernel<<<DIM * NN / 8 / 256, 256>>>();
    gemm_k<1><<<dim3(NN / 128, 2), 512, DSMEM>>>(adjh, NN, NN / 64, b, out);
}